// round 5
// baseline (speedup 1.0000x reference)
#include <cuda_runtime.h>
#include <math.h>

#define W_IMG 1024
#define N_PIX (W_IMG * W_IMG)
#define MAXB 4
#define NTH 256

// stats per batch: [0..2]=sum q_c^2, [3..5]=sum k_c^2, [6..14]=sum q_c*k_d
__device__ float g_stats[MAXB][16];
__device__ float g_M[MAXB][12];
// planar k scratch: [b][c][pix]
__device__ float g_k[(size_t)MAXB * 3 * N_PIX];

__global__ void k_zero() {
    int i = threadIdx.x;
    if (i < MAXB * 16) ((float*)g_stats)[i] = 0.0f;
}

// ---------------------------------------------------------------------------
// Kernel A: x (channels-last) -> k (planar scratch) + sum k^2 stats.
// 4x4 patch per thread.
// ---------------------------------------------------------------------------
__global__ __launch_bounds__(NTH) void k_conv_k(const float* __restrict__ x,
                                                const float* __restrict__ kC,
                                                const float* __restrict__ kD) {
    __shared__ float red[NTH / 32][3];

    const int b = blockIdx.z;
    const int warp = threadIdx.x >> 5, lane = threadIdx.x & 31;
    const int wx0 = blockIdx.x * 128;
    const int px0 = wx0 + lane * 4;
    const int y0 = blockIdx.y * 32 + warp * 4;

    const float* __restrict__ xb = x + (size_t)b * 3 * N_PIX;
    float* __restrict__ kb = g_k + (size_t)b * 3 * N_PIX;

    const bool is_e = (lane == 0) | (lane == 31);
    const int ex = (lane == 0) ? wx0 - 1 : wx0 + 128;
    const bool ex_ok = (unsigned)ex < (unsigned)W_IMG;

    float cw[9], dw[27];
#pragma unroll
    for (int i = 0; i < 9; i++) cw[i] = kC[i];
#pragma unroll
    for (int i = 0; i < 27; i++) dw[i] = kD[i];

    float p0 = 0.f, p1 = 0.f, p2 = 0.f;

    float a0[3][4], a1[3][4], a2[3][4];
#pragma unroll
    for (int c = 0; c < 3; c++)
#pragma unroll
        for (int j = 0; j < 4; j++) { a0[c][j] = a1[c][j] = a2[c][j] = 0.f; }

#pragma unroll
    for (int iy = 0; iy < 6; iy++) {
        const int yin = y0 + iy - 1;
        const bool yok = (unsigned)yin < (unsigned)W_IMG;

        float hm[3][4];
#pragma unroll
        for (int c = 0; c < 3; c++)
#pragma unroll
            for (int j = 0; j < 4; j++) hm[c][j] = 0.f;

        if (yok) {
            const float4* p4 = (const float4*)(xb + (size_t)(yin * W_IMG + px0) * 3);
            float4 v0 = p4[0], v1 = p4[1], v2 = p4[2];
            float g[4][3] = {{v0.x, v0.y, v0.z}, {v0.w, v1.x, v1.y},
                             {v1.z, v1.w, v2.x}, {v2.y, v2.z, v2.w}};
#pragma unroll
            for (int j = 0; j < 4; j++)
#pragma unroll
                for (int c = 0; c < 3; c++)
                    hm[c][j] = cw[c * 3] * g[j][0] + cw[c * 3 + 1] * g[j][1] + cw[c * 3 + 2] * g[j][2];
        }
        float he[3] = {0.f, 0.f, 0.f};
        if (yok && is_e && ex_ok) {
            const float* pe = xb + (size_t)(yin * W_IMG + ex) * 3;
            float g0 = pe[0], g1 = pe[1], g2 = pe[2];
#pragma unroll
            for (int c = 0; c < 3; c++)
                he[c] = cw[c * 3] * g0 + cw[c * 3 + 1] * g1 + cw[c * 3 + 2] * g2;
        }
        float hl[3], hr[3];
#pragma unroll
        for (int c = 0; c < 3; c++) {
            hl[c] = __shfl_up_sync(0xffffffffu, hm[c][3], 1);
            hr[c] = __shfl_down_sync(0xffffffffu, hm[c][0], 1);
            if (lane == 0) hl[c] = he[c];
            if (lane == 31) hr[c] = he[c];
        }
#pragma unroll
        for (int c = 0; c < 3; c++)
#pragma unroll
            for (int j = 0; j < 4; j++) {
                float L = j ? hm[c][j - 1] : hl[c];
                float M_ = hm[c][j];
                float R = (j < 3) ? hm[c][j + 1] : hr[c];
                a0[c][j] += dw[c * 9 + 6] * L + dw[c * 9 + 7] * M_ + dw[c * 9 + 8] * R;
                a1[c][j] += dw[c * 9 + 3] * L + dw[c * 9 + 4] * M_ + dw[c * 9 + 5] * R;
                a2[c][j] += dw[c * 9 + 0] * L + dw[c * 9 + 1] * M_ + dw[c * 9 + 2] * R;
            }
        if (iy >= 2) {
            const int yout = y0 + iy - 2;
            const size_t o = (size_t)yout * W_IMG + px0;
#pragma unroll
            for (int c = 0; c < 3; c++) {
                float v0 = a0[c][0], v1 = a0[c][1], v2 = a0[c][2], v3 = a0[c][3];
                *(float4*)(kb + c * (size_t)N_PIX + o) = make_float4(v0, v1, v2, v3);
                float s = v0 * v0 + v1 * v1 + v2 * v2 + v3 * v3;
                if (c == 0) p0 += s;
                else if (c == 1) p1 += s;
                else p2 += s;
            }
        }
#pragma unroll
        for (int c = 0; c < 3; c++)
#pragma unroll
            for (int j = 0; j < 4; j++) {
                a0[c][j] = a1[c][j];
                a1[c][j] = a2[c][j];
                a2[c][j] = 0.f;
            }
    }

#pragma unroll
    for (int o = 16; o; o >>= 1) {
        p0 += __shfl_down_sync(0xffffffffu, p0, o);
        p1 += __shfl_down_sync(0xffffffffu, p1, o);
        p2 += __shfl_down_sync(0xffffffffu, p2, o);
    }
    if (lane == 0) { red[warp][0] = p0; red[warp][1] = p1; red[warp][2] = p2; }
    __syncthreads();
    if (threadIdx.x < 3) {
        float t = 0.f;
#pragma unroll
        for (int w2 = 0; w2 < NTH / 32; w2++) t += red[w2][threadIdx.x];
        atomicAdd(&g_stats[b][3 + threadIdx.x], t);
    }
}

// ---------------------------------------------------------------------------
// Kernel B: fhigh (planar) -> q; read k scratch; accumulate q^2 and q*k.
// ---------------------------------------------------------------------------
__global__ __launch_bounds__(NTH) void k_conv_q(const float* __restrict__ fhigh,
                                                const float* __restrict__ qC,
                                                const float* __restrict__ qD) {
    __shared__ float red[NTH / 32][12];

    const int b = blockIdx.z;
    const int warp = threadIdx.x >> 5, lane = threadIdx.x & 31;
    const int wx0 = blockIdx.x * 128;
    const int px0 = wx0 + lane * 4;
    const int y0 = blockIdx.y * 32 + warp * 4;

    const float* __restrict__ fb = fhigh + (size_t)b * 3 * N_PIX;
    const float* __restrict__ kb = g_k + (size_t)b * 3 * N_PIX;

    const bool is_e = (lane == 0) | (lane == 31);
    const int ex = (lane == 0) ? wx0 - 1 : wx0 + 128;
    const bool ex_ok = (unsigned)ex < (unsigned)W_IMG;

    float cw[9], dw[27];
#pragma unroll
    for (int i = 0; i < 9; i++) cw[i] = qC[i];
#pragma unroll
    for (int i = 0; i < 27; i++) dw[i] = qD[i];

    float p[12];
#pragma unroll
    for (int i = 0; i < 12; i++) p[i] = 0.f;

    float a0[3][4], a1[3][4], a2[3][4];
#pragma unroll
    for (int c = 0; c < 3; c++)
#pragma unroll
        for (int j = 0; j < 4; j++) { a0[c][j] = a1[c][j] = a2[c][j] = 0.f; }

#pragma unroll
    for (int iy = 0; iy < 6; iy++) {
        const int yin = y0 + iy - 1;
        const bool yok = (unsigned)yin < (unsigned)W_IMG;

        float hm[3][4];
#pragma unroll
        for (int c = 0; c < 3; c++)
#pragma unroll
            for (int j = 0; j < 4; j++) hm[c][j] = 0.f;

        if (yok) {
            const size_t o = (size_t)yin * W_IMG + px0;
            float4 f0 = *(const float4*)(fb + o);
            float4 f1 = *(const float4*)(fb + o + N_PIX);
            float4 f2 = *(const float4*)(fb + o + 2 * N_PIX);
            float g[4][3] = {{f0.x, f1.x, f2.x}, {f0.y, f1.y, f2.y},
                             {f0.z, f1.z, f2.z}, {f0.w, f1.w, f2.w}};
#pragma unroll
            for (int j = 0; j < 4; j++)
#pragma unroll
                for (int c = 0; c < 3; c++)
                    hm[c][j] = cw[c * 3] * g[j][0] + cw[c * 3 + 1] * g[j][1] + cw[c * 3 + 2] * g[j][2];
        }
        float he[3] = {0.f, 0.f, 0.f};
        if (yok && is_e && ex_ok) {
            const size_t o = (size_t)yin * W_IMG + ex;
            float g0 = fb[o], g1 = fb[o + N_PIX], g2 = fb[o + 2 * N_PIX];
#pragma unroll
            for (int c = 0; c < 3; c++)
                he[c] = cw[c * 3] * g0 + cw[c * 3 + 1] * g1 + cw[c * 3 + 2] * g2;
        }
        float hl[3], hr[3];
#pragma unroll
        for (int c = 0; c < 3; c++) {
            hl[c] = __shfl_up_sync(0xffffffffu, hm[c][3], 1);
            hr[c] = __shfl_down_sync(0xffffffffu, hm[c][0], 1);
            if (lane == 0) hl[c] = he[c];
            if (lane == 31) hr[c] = he[c];
        }
#pragma unroll
        for (int c = 0; c < 3; c++)
#pragma unroll
            for (int j = 0; j < 4; j++) {
                float L = j ? hm[c][j - 1] : hl[c];
                float M_ = hm[c][j];
                float R = (j < 3) ? hm[c][j + 1] : hr[c];
                a0[c][j] += dw[c * 9 + 6] * L + dw[c * 9 + 7] * M_ + dw[c * 9 + 8] * R;
                a1[c][j] += dw[c * 9 + 3] * L + dw[c * 9 + 4] * M_ + dw[c * 9 + 5] * R;
                a2[c][j] += dw[c * 9 + 0] * L + dw[c * 9 + 1] * M_ + dw[c * 9 + 2] * R;
            }
        if (iy >= 2) {
            const int yout = y0 + iy - 2;
            const size_t o = (size_t)yout * W_IMG + px0;
            float4 k0 = *(const float4*)(kb + o);
            float4 k1 = *(const float4*)(kb + (size_t)N_PIX + o);
            float4 k2 = *(const float4*)(kb + 2 * (size_t)N_PIX + o);
            float kv[3][4] = {{k0.x, k0.y, k0.z, k0.w},
                              {k1.x, k1.y, k1.z, k1.w},
                              {k2.x, k2.y, k2.z, k2.w}};
#pragma unroll
            for (int c = 0; c < 3; c++)
#pragma unroll
                for (int j = 0; j < 4; j++) {
                    float q = a0[c][j];
                    p[c] += q * q;
                    p[3 + c * 3 + 0] += q * kv[0][j];
                    p[3 + c * 3 + 1] += q * kv[1][j];
                    p[3 + c * 3 + 2] += q * kv[2][j];
                }
        }
#pragma unroll
        for (int c = 0; c < 3; c++)
#pragma unroll
            for (int j = 0; j < 4; j++) {
                a0[c][j] = a1[c][j];
                a1[c][j] = a2[c][j];
                a2[c][j] = 0.f;
            }
    }

#pragma unroll
    for (int i = 0; i < 12; i++)
#pragma unroll
        for (int o = 16; o; o >>= 1)
            p[i] += __shfl_down_sync(0xffffffffu, p[i], o);
    if (lane == 0) {
#pragma unroll
        for (int i = 0; i < 12; i++) red[warp][i] = p[i];
    }
    __syncthreads();
    if (threadIdx.x < 12) {
        float t = 0.f;
#pragma unroll
        for (int w2 = 0; w2 < NTH / 32; w2++) t += red[w2][threadIdx.x];
        int dst = (threadIdx.x < 3) ? threadIdx.x : (3 + threadIdx.x);  // 0..2 -> q^2, 3..11 -> qk at 6..14
        atomicAdd(&g_stats[b][dst], t);
    }
}

__global__ void k_attn(const float* __restrict__ proj_w,
                       const float* __restrict__ temp, int B) {
    if (threadIdx.x != 0 || blockIdx.x != 0) return;
    float T = temp[0];
    for (int b = 0; b < B; b++) {
        float nq[3], nk[3];
#pragma unroll
        for (int c = 0; c < 3; c++) {
            nq[c] = fmaxf(sqrtf(g_stats[b][c]), 1e-12f);
            nk[c] = fmaxf(sqrtf(g_stats[b][3 + c]), 1e-12f);
        }
        float a[3][3];
#pragma unroll
        for (int c = 0; c < 3; c++)
#pragma unroll
            for (int d = 0; d < 3; d++)
                a[c][d] = g_stats[b][6 + c * 3 + d] / (nq[c] * nk[d]) * T;
#pragma unroll
        for (int c = 0; c < 3; c++) {
            float mx = fmaxf(a[c][0], fmaxf(a[c][1], a[c][2]));
            float e0 = expf(a[c][0] - mx);
            float e1 = expf(a[c][1] - mx);
            float e2 = expf(a[c][2] - mx);
            float inv = 1.f / (e0 + e1 + e2);
            a[c][0] = e0 * inv; a[c][1] = e1 * inv; a[c][2] = e2 * inv;
        }
#pragma unroll
        for (int co = 0; co < 3; co++)
#pragma unroll
            for (int d = 0; d < 3; d++) {
                float m = 0.f;
#pragma unroll
                for (int c = 0; c < 3; c++) m += proj_w[co * 3 + c] * a[c][d];
                g_M[b][co * 3 + d] = m;
            }
    }
}

// ---------------------------------------------------------------------------
// Kernel D: pure streaming map. Read planar k scratch, apply M + bias, write
// channels-last output. 4 pixels per thread, all float4.
// ---------------------------------------------------------------------------
__global__ __launch_bounds__(NTH) void k_out2(const float* __restrict__ proj_b,
                                              float* __restrict__ out) {
    const int b = blockIdx.y;
    const size_t pix0 = ((size_t)blockIdx.x * NTH + threadIdx.x) * 4;
    if (pix0 >= N_PIX) return;

    const float* __restrict__ kb = g_k + (size_t)b * 3 * N_PIX;

    float m[9];
#pragma unroll
    for (int i = 0; i < 9; i++) m[i] = g_M[b][i];
    const float b0 = proj_b[0], b1 = proj_b[1], b2 = proj_b[2];

    float4 k0 = *(const float4*)(kb + pix0);
    float4 k1 = *(const float4*)(kb + N_PIX + pix0);
    float4 k2 = *(const float4*)(kb + 2 * (size_t)N_PIX + pix0);

    float kv[3][4] = {{k0.x, k0.y, k0.z, k0.w},
                      {k1.x, k1.y, k1.z, k1.w},
                      {k2.x, k2.y, k2.z, k2.w}};
    float o[12];
#pragma unroll
    for (int j = 0; j < 4; j++) {
        o[j * 3 + 0] = m[0] * kv[0][j] + m[1] * kv[1][j] + m[2] * kv[2][j] + b0;
        o[j * 3 + 1] = m[3] * kv[0][j] + m[4] * kv[1][j] + m[5] * kv[2][j] + b1;
        o[j * 3 + 2] = m[6] * kv[0][j] + m[7] * kv[1][j] + m[8] * kv[2][j] + b2;
    }
    float4* q4 = (float4*)(out + ((size_t)b * N_PIX + pix0) * 3);
    q4[0] = make_float4(o[0], o[1], o[2], o[3]);
    q4[1] = make_float4(o[4], o[5], o[6], o[7]);
    q4[2] = make_float4(o[8], o[9], o[10], o[11]);
}

extern "C" void kernel_launch(void* const* d_in, const int* in_sizes, int n_in,
                              void* d_out, int out_size) {
    const float* x     = (const float*)d_in[0];
    const float* fhigh = (const float*)d_in[1];
    const float* qCw   = (const float*)d_in[2];
    const float* qdw   = (const float*)d_in[3];
    const float* kCw   = (const float*)d_in[4];
    const float* kdw   = (const float*)d_in[5];
    const float* projw = (const float*)d_in[6];
    const float* projb = (const float*)d_in[7];
    const float* temp  = (const float*)d_in[8];
    float* out = (float*)d_out;

    int B = in_sizes[0] / (N_PIX * 3);
    if (B > MAXB) B = MAXB;

    k_zero<<<1, 128>>>();
    dim3 grid(W_IMG / 128, W_IMG / 32, B);
    k_conv_k<<<grid, NTH>>>(x, kCw, kdw);
    k_conv_q<<<grid, NTH>>>(fhigh, qCw, qdw);
    k_attn<<<1, 1>>>(projw, temp, B);
    dim3 gridD(N_PIX / (NTH * 4), B);
    k_out2<<<gridD, NTH>>>(projb, out);
}

// round 6
// speedup vs baseline: 1.1508x; 1.1508x over previous
#include <cuda_runtime.h>
#include <math.h>

#define W_IMG 1024
#define N_PIX (W_IMG * W_IMG)
#define MAXB 8
#define NTH 256

// stats per batch: [0..2]=sum q_c^2, [3..5]=sum k_c^2, [6..14]=sum q_c*k_d
__device__ float g_stats[MAXB][16];

__global__ void k_zero() {
    int i = threadIdx.x;
    if (i < MAXB * 16) ((float*)g_stats)[i] = 0.0f;
}

// ---------------------------------------------------------------------------
// k_stats: 4x4 patch per thread. K path first (store k patch), then Q path
// accumulating the 15 per-batch statistics on the fly. (R4 proven version.)
// ---------------------------------------------------------------------------
__global__ __launch_bounds__(NTH) void k_stats(const float* __restrict__ x,
                                               const float* __restrict__ fhigh,
                                               const float* __restrict__ qC,
                                               const float* __restrict__ qD,
                                               const float* __restrict__ kC,
                                               const float* __restrict__ kD) {
    __shared__ float red[NTH / 32][15];

    const int b = blockIdx.z;
    const int warp = threadIdx.x >> 5, lane = threadIdx.x & 31;
    const int wx0 = blockIdx.x * 128;
    const int px0 = wx0 + lane * 4;
    const int y0 = blockIdx.y * 32 + warp * 4;

    const float* __restrict__ xb = x + (size_t)b * 3 * N_PIX;
    const float* __restrict__ fb = fhigh + (size_t)b * 3 * N_PIX;

    const bool is_e = (lane == 0) | (lane == 31);
    const int ex = (lane == 0) ? wx0 - 1 : wx0 + 128;
    const bool ex_ok = (unsigned)ex < (unsigned)W_IMG;

    float p[15];
#pragma unroll
    for (int i = 0; i < 15; i++) p[i] = 0.f;

    float kout[3][4][4];  // [ch][row][j]

    // ================= K path (input x, channels-last) =================
    {
        float cw[9], dw[27];
#pragma unroll
        for (int i = 0; i < 9; i++) cw[i] = kC[i];
#pragma unroll
        for (int i = 0; i < 27; i++) dw[i] = kD[i];

        float a0[3][4], a1[3][4], a2[3][4];
#pragma unroll
        for (int c = 0; c < 3; c++)
#pragma unroll
            for (int j = 0; j < 4; j++) { a0[c][j] = a1[c][j] = a2[c][j] = 0.f; }

#pragma unroll
        for (int iy = 0; iy < 6; iy++) {
            const int yin = y0 + iy - 1;
            const bool yok = (unsigned)yin < (unsigned)W_IMG;

            float hm[3][4];
#pragma unroll
            for (int c = 0; c < 3; c++)
#pragma unroll
                for (int j = 0; j < 4; j++) hm[c][j] = 0.f;

            if (yok) {
                const float4* p4 = (const float4*)(xb + (size_t)(yin * W_IMG + px0) * 3);
                float4 v0 = p4[0], v1 = p4[1], v2 = p4[2];
                float g[4][3] = {{v0.x, v0.y, v0.z}, {v0.w, v1.x, v1.y},
                                 {v1.z, v1.w, v2.x}, {v2.y, v2.z, v2.w}};
#pragma unroll
                for (int j = 0; j < 4; j++)
#pragma unroll
                    for (int c = 0; c < 3; c++)
                        hm[c][j] = cw[c * 3] * g[j][0] + cw[c * 3 + 1] * g[j][1] + cw[c * 3 + 2] * g[j][2];
            }
            float he[3] = {0.f, 0.f, 0.f};
            if (yok && is_e && ex_ok) {
                const float* pe = xb + (size_t)(yin * W_IMG + ex) * 3;
                float g0 = pe[0], g1 = pe[1], g2 = pe[2];
#pragma unroll
                for (int c = 0; c < 3; c++)
                    he[c] = cw[c * 3] * g0 + cw[c * 3 + 1] * g1 + cw[c * 3 + 2] * g2;
            }
            float hl[3], hr[3];
#pragma unroll
            for (int c = 0; c < 3; c++) {
                hl[c] = __shfl_up_sync(0xffffffffu, hm[c][3], 1);
                hr[c] = __shfl_down_sync(0xffffffffu, hm[c][0], 1);
                if (lane == 0) hl[c] = he[c];
                if (lane == 31) hr[c] = he[c];
            }
#pragma unroll
            for (int c = 0; c < 3; c++)
#pragma unroll
                for (int j = 0; j < 4; j++) {
                    float L = j ? hm[c][j - 1] : hl[c];
                    float M_ = hm[c][j];
                    float R = (j < 3) ? hm[c][j + 1] : hr[c];
                    a0[c][j] += dw[c * 9 + 6] * L + dw[c * 9 + 7] * M_ + dw[c * 9 + 8] * R;
                    a1[c][j] += dw[c * 9 + 3] * L + dw[c * 9 + 4] * M_ + dw[c * 9 + 5] * R;
                    a2[c][j] += dw[c * 9 + 0] * L + dw[c * 9 + 1] * M_ + dw[c * 9 + 2] * R;
                }
            if (iy >= 2) {
                const int r = iy - 2;
#pragma unroll
                for (int c = 0; c < 3; c++)
#pragma unroll
                    for (int j = 0; j < 4; j++) {
                        float v = a0[c][j];
                        kout[c][r][j] = v;
                        p[3 + c] += v * v;
                    }
            }
#pragma unroll
            for (int c = 0; c < 3; c++)
#pragma unroll
                for (int j = 0; j < 4; j++) {
                    a0[c][j] = a1[c][j];
                    a1[c][j] = a2[c][j];
                    a2[c][j] = 0.f;
                }
        }
    }

    // ================= Q path (input fhigh, planar) =================
    {
        float cw[9], dw[27];
#pragma unroll
        for (int i = 0; i < 9; i++) cw[i] = qC[i];
#pragma unroll
        for (int i = 0; i < 27; i++) dw[i] = qD[i];

        float a0[3][4], a1[3][4], a2[3][4];
#pragma unroll
        for (int c = 0; c < 3; c++)
#pragma unroll
            for (int j = 0; j < 4; j++) { a0[c][j] = a1[c][j] = a2[c][j] = 0.f; }

#pragma unroll
        for (int iy = 0; iy < 6; iy++) {
            const int yin = y0 + iy - 1;
            const bool yok = (unsigned)yin < (unsigned)W_IMG;

            float hm[3][4];
#pragma unroll
            for (int c = 0; c < 3; c++)
#pragma unroll
                for (int j = 0; j < 4; j++) hm[c][j] = 0.f;

            if (yok) {
                const size_t o = (size_t)yin * W_IMG + px0;
                float4 f0 = *(const float4*)(fb + o);
                float4 f1 = *(const float4*)(fb + o + N_PIX);
                float4 f2 = *(const float4*)(fb + o + 2 * N_PIX);
                float g[4][3] = {{f0.x, f1.x, f2.x}, {f0.y, f1.y, f2.y},
                                 {f0.z, f1.z, f2.z}, {f0.w, f1.w, f2.w}};
#pragma unroll
                for (int j = 0; j < 4; j++)
#pragma unroll
                    for (int c = 0; c < 3; c++)
                        hm[c][j] = cw[c * 3] * g[j][0] + cw[c * 3 + 1] * g[j][1] + cw[c * 3 + 2] * g[j][2];
            }
            float he[3] = {0.f, 0.f, 0.f};
            if (yok && is_e && ex_ok) {
                const size_t o = (size_t)yin * W_IMG + ex;
                float g0 = fb[o], g1 = fb[o + N_PIX], g2 = fb[o + 2 * N_PIX];
#pragma unroll
                for (int c = 0; c < 3; c++)
                    he[c] = cw[c * 3] * g0 + cw[c * 3 + 1] * g1 + cw[c * 3 + 2] * g2;
            }
            float hl[3], hr[3];
#pragma unroll
            for (int c = 0; c < 3; c++) {
                hl[c] = __shfl_up_sync(0xffffffffu, hm[c][3], 1);
                hr[c] = __shfl_down_sync(0xffffffffu, hm[c][0], 1);
                if (lane == 0) hl[c] = he[c];
                if (lane == 31) hr[c] = he[c];
            }
#pragma unroll
            for (int c = 0; c < 3; c++)
#pragma unroll
                for (int j = 0; j < 4; j++) {
                    float L = j ? hm[c][j - 1] : hl[c];
                    float M_ = hm[c][j];
                    float R = (j < 3) ? hm[c][j + 1] : hr[c];
                    a0[c][j] += dw[c * 9 + 6] * L + dw[c * 9 + 7] * M_ + dw[c * 9 + 8] * R;
                    a1[c][j] += dw[c * 9 + 3] * L + dw[c * 9 + 4] * M_ + dw[c * 9 + 5] * R;
                    a2[c][j] += dw[c * 9 + 0] * L + dw[c * 9 + 1] * M_ + dw[c * 9 + 2] * R;
                }
            if (iy >= 2) {
                const int r = iy - 2;
#pragma unroll
                for (int c = 0; c < 3; c++)
#pragma unroll
                    for (int j = 0; j < 4; j++) {
                        float q = a0[c][j];
                        p[c] += q * q;
#pragma unroll
                        for (int d = 0; d < 3; d++)
                            p[6 + c * 3 + d] += q * kout[d][r][j];
                    }
            }
#pragma unroll
            for (int c = 0; c < 3; c++)
#pragma unroll
                for (int j = 0; j < 4; j++) {
                    a0[c][j] = a1[c][j];
                    a1[c][j] = a2[c][j];
                    a2[c][j] = 0.f;
                }
        }
    }

    // reduce
#pragma unroll
    for (int i = 0; i < 15; i++)
#pragma unroll
        for (int o = 16; o; o >>= 1)
            p[i] += __shfl_down_sync(0xffffffffu, p[i], o);
    if (lane == 0) {
#pragma unroll
        for (int i = 0; i < 15; i++) red[warp][i] = p[i];
    }
    __syncthreads();
    if (threadIdx.x < 15) {
        float t = 0.f;
#pragma unroll
        for (int w2 = 0; w2 < NTH / 32; w2++) t += red[w2][threadIdx.x];
        atomicAdd(&g_stats[b][threadIdx.x], t);
    }
}

// ---------------------------------------------------------------------------
// k_out: 4-wide x 8-tall patch per thread. Computes M = proj_w @ softmax(attn)
// per block in a prologue (no separate k_attn kernel), then k conv + M map.
// ---------------------------------------------------------------------------
__global__ __launch_bounds__(NTH) void k_out(const float* __restrict__ x,
                                             const float* __restrict__ kC,
                                             const float* __restrict__ kD,
                                             const float* __restrict__ proj_w,
                                             const float* __restrict__ proj_b,
                                             const float* __restrict__ temp,
                                             float* __restrict__ out) {
    __shared__ float sM[9];

    const int b = blockIdx.z;

    // --- prologue: one thread computes the 3x3 matrix M for this batch ---
    if (threadIdx.x == 0) {
        float T = temp[0];
        float nq[3], nk[3];
#pragma unroll
        for (int c = 0; c < 3; c++) {
            nq[c] = fmaxf(sqrtf(g_stats[b][c]), 1e-12f);
            nk[c] = fmaxf(sqrtf(g_stats[b][3 + c]), 1e-12f);
        }
        float a[3][3];
#pragma unroll
        for (int c = 0; c < 3; c++)
#pragma unroll
            for (int d = 0; d < 3; d++)
                a[c][d] = g_stats[b][6 + c * 3 + d] / (nq[c] * nk[d]) * T;
#pragma unroll
        for (int c = 0; c < 3; c++) {
            float mx = fmaxf(a[c][0], fmaxf(a[c][1], a[c][2]));
            float e0 = expf(a[c][0] - mx);
            float e1 = expf(a[c][1] - mx);
            float e2 = expf(a[c][2] - mx);
            float inv = 1.f / (e0 + e1 + e2);
            a[c][0] = e0 * inv; a[c][1] = e1 * inv; a[c][2] = e2 * inv;
        }
#pragma unroll
        for (int co = 0; co < 3; co++)
#pragma unroll
            for (int d = 0; d < 3; d++) {
                float mm = 0.f;
#pragma unroll
                for (int c = 0; c < 3; c++) mm += proj_w[co * 3 + c] * a[c][d];
                sM[co * 3 + d] = mm;
            }
    }
    __syncthreads();

    const int warp = threadIdx.x >> 5, lane = threadIdx.x & 31;
    const int wx0 = blockIdx.x * 128;
    const int px0 = wx0 + lane * 4;
    const int y0 = blockIdx.y * 64 + warp * 8;   // 8 output rows per warp

    const float* __restrict__ xb = x + (size_t)b * 3 * N_PIX;

    const bool is_e = (lane == 0) | (lane == 31);
    const int ex = (lane == 0) ? wx0 - 1 : wx0 + 128;
    const bool ex_ok = (unsigned)ex < (unsigned)W_IMG;

    float cw[9], dw[27];
#pragma unroll
    for (int i = 0; i < 9; i++) cw[i] = kC[i];
#pragma unroll
    for (int i = 0; i < 27; i++) dw[i] = kD[i];

    float m[9];
#pragma unroll
    for (int i = 0; i < 9; i++) m[i] = sM[i];
    const float b0 = proj_b[0], b1 = proj_b[1], b2 = proj_b[2];

    float a0[3][4], a1[3][4], a2[3][4];
#pragma unroll
    for (int c = 0; c < 3; c++)
#pragma unroll
        for (int j = 0; j < 4; j++) { a0[c][j] = a1[c][j] = a2[c][j] = 0.f; }

#pragma unroll
    for (int iy = 0; iy < 10; iy++) {
        const int yin = y0 + iy - 1;
        const bool yok = (unsigned)yin < (unsigned)W_IMG;

        float hm[3][4];
#pragma unroll
        for (int c = 0; c < 3; c++)
#pragma unroll
            for (int j = 0; j < 4; j++) hm[c][j] = 0.f;

        if (yok) {
            const float4* p4 = (const float4*)(xb + (size_t)(yin * W_IMG + px0) * 3);
            float4 v0 = p4[0], v1 = p4[1], v2 = p4[2];
            float g[4][3] = {{v0.x, v0.y, v0.z}, {v0.w, v1.x, v1.y},
                             {v1.z, v1.w, v2.x}, {v2.y, v2.z, v2.w}};
#pragma unroll
            for (int j = 0; j < 4; j++)
#pragma unroll
                for (int c = 0; c < 3; c++)
                    hm[c][j] = cw[c * 3] * g[j][0] + cw[c * 3 + 1] * g[j][1] + cw[c * 3 + 2] * g[j][2];
        }
        float he[3] = {0.f, 0.f, 0.f};
        if (yok && is_e && ex_ok) {
            const float* pe = xb + (size_t)(yin * W_IMG + ex) * 3;
            float g0 = pe[0], g1 = pe[1], g2 = pe[2];
#pragma unroll
            for (int c = 0; c < 3; c++)
                he[c] = cw[c * 3] * g0 + cw[c * 3 + 1] * g1 + cw[c * 3 + 2] * g2;
        }
        float hl[3], hr[3];
#pragma unroll
        for (int c = 0; c < 3; c++) {
            hl[c] = __shfl_up_sync(0xffffffffu, hm[c][3], 1);
            hr[c] = __shfl_down_sync(0xffffffffu, hm[c][0], 1);
            if (lane == 0) hl[c] = he[c];
            if (lane == 31) hr[c] = he[c];
        }
#pragma unroll
        for (int c = 0; c < 3; c++)
#pragma unroll
            for (int j = 0; j < 4; j++) {
                float L = j ? hm[c][j - 1] : hl[c];
                float M_ = hm[c][j];
                float R = (j < 3) ? hm[c][j + 1] : hr[c];
                a0[c][j] += dw[c * 9 + 6] * L + dw[c * 9 + 7] * M_ + dw[c * 9 + 8] * R;
                a1[c][j] += dw[c * 9 + 3] * L + dw[c * 9 + 4] * M_ + dw[c * 9 + 5] * R;
                a2[c][j] += dw[c * 9 + 0] * L + dw[c * 9 + 1] * M_ + dw[c * 9 + 2] * R;
            }
        if (iy >= 2) {
            const int yout = y0 + iy - 2;
            float o[12];
#pragma unroll
            for (int j = 0; j < 4; j++) {
                float k0 = a0[0][j], k1 = a0[1][j], k2 = a0[2][j];
                o[j * 3 + 0] = m[0] * k0 + m[1] * k1 + m[2] * k2 + b0;
                o[j * 3 + 1] = m[3] * k0 + m[4] * k1 + m[5] * k2 + b1;
                o[j * 3 + 2] = m[6] * k0 + m[7] * k1 + m[8] * k2 + b2;
            }
            float4* q4 = (float4*)(out + ((size_t)b * N_PIX + (size_t)yout * W_IMG + px0) * 3);
            q4[0] = make_float4(o[0], o[1], o[2], o[3]);
            q4[1] = make_float4(o[4], o[5], o[6], o[7]);
            q4[2] = make_float4(o[8], o[9], o[10], o[11]);
        }
#pragma unroll
        for (int c = 0; c < 3; c++)
#pragma unroll
            for (int j = 0; j < 4; j++) {
                a0[c][j] = a1[c][j];
                a1[c][j] = a2[c][j];
                a2[c][j] = 0.f;
            }
    }
}

extern "C" void kernel_launch(void* const* d_in, const int* in_sizes, int n_in,
                              void* d_out, int out_size) {
    const float* x     = (const float*)d_in[0];
    const float* fhigh = (const float*)d_in[1];
    const float* qCw   = (const float*)d_in[2];
    const float* qdw   = (const float*)d_in[3];
    const float* kCw   = (const float*)d_in[4];
    const float* kdw   = (const float*)d_in[5];
    const float* projw = (const float*)d_in[6];
    const float* projb = (const float*)d_in[7];
    const float* temp  = (const float*)d_in[8];
    float* out = (float*)d_out;

    int B = in_sizes[0] / (N_PIX * 3);
    if (B > MAXB) B = MAXB;

    k_zero<<<1, 128>>>();
    dim3 gridS(W_IMG / 128, W_IMG / 32, B);
    k_stats<<<gridS, NTH>>>(x, fhigh, qCw, qdw, kCw, kdw);
    dim3 gridO(W_IMG / 128, W_IMG / 64, B);
    k_out<<<gridO, NTH>>>(x, kCw, kdw, projw, projb, temp, out);
}